// round 12
// baseline (speedup 1.0000x reference)
#include <cuda_runtime.h>
#include <cuda_fp16.h>
#include <cstdint>

// Problem constants
#define B_    2
#define N_    2048
#define C_    256
#define COOR  3
#define H_    8
#define D_    64
#define E_    192      // D_*COOR
#define DI    512      // dim_inner = H_*D_
#define BN    4096     // B_*N_
#define BH    16       // B_*H_

// Scratch (device globals — no runtime allocation)
// Split format: uint2 = (hi fp16x2, lo fp16x2) for 2 adjacent K elements.
// e-dimension uses reordered index e' = c*64 + d (permutation-invariant for dots).
__device__ uint2 g_xt2[(size_t)COOR * BN * (C_ / 2)];        // [c][m][ipair]
__device__ uint2 g_w2 [(size_t)3 * DI * (C_ / 2)];           // [mat][o][ipair]
__device__ uint2 g_wo2[(size_t)C_ * (DI / 2)];               // [o][ipair]
__device__ uint2 g_q2 [(size_t)BH * N_ * (E_ / 2)];          // [bh][n][e'pair]
__device__ uint2 g_k2 [(size_t)BH * N_ * (E_ / 2)];
__device__ float g_v  [(size_t)BH * N_ * E_];                // [bh][n][e'] fp32
__device__ uint2 g_v2 [(size_t)BH * E_ * (N_ / 2)];          // [bh][e'][npair]
__device__ uint2 g_p2 [(size_t)BH * N_ * (N_ / 2)];          // [bh][i][jpair] unnormalized exp
__device__ float g_rsum[(size_t)BH * N_];                    // softmax row sums
__device__ uint2 g_o22[(size_t)COOR * BN * (DI / 2)];        // [c][m][dipair]

// ---------------------------------------------------------------------------
// helpers
// ---------------------------------------------------------------------------
__device__ __forceinline__ uint32_t smem_u32(const void* p) {
    uint32_t a;
    asm("{ .reg .u64 t; cvta.to.shared.u64 t, %1; cvt.u32.u64 %0, t; }" : "=r"(a) : "l"(p));
    return a;
}

__device__ __forceinline__ void cp16(uint32_t s, const void* g) {
    asm volatile("cp.async.cg.shared.global [%0], [%1], 16;" :: "r"(s), "l"(g) : "memory");
}

__device__ __forceinline__ uint2 split2h(float2 v) {
    __half hx = __float2half_rn(v.x);
    __half hy = __float2half_rn(v.y);
    float lx = v.x - __half2float(hx);
    float ly = v.y - __half2float(hy);
    __half lxh = __float2half_rn(lx);
    __half lyh = __float2half_rn(ly);
    uint2 r;
    r.x = ((uint32_t)__half_as_ushort(hy) << 16) | (uint32_t)__half_as_ushort(hx);
    r.y = ((uint32_t)__half_as_ushort(lyh) << 16) | (uint32_t)__half_as_ushort(lxh);
    return r;
}

__device__ __forceinline__ void mma_fp16_k16(float* c, const uint32_t* a, const uint32_t* b) {
    asm volatile(
        "mma.sync.aligned.m16n8k16.row.col.f32.f16.f16.f32 "
        "{%0,%1,%2,%3},{%4,%5,%6,%7},{%8,%9},{%0,%1,%2,%3};"
        : "+f"(c[0]), "+f"(c[1]), "+f"(c[2]), "+f"(c[3])
        : "r"(a[0]), "r"(a[1]), "r"(a[2]), "r"(a[3]), "r"(b[0]), "r"(b[1]));
}

// ---------------------------------------------------------------------------
// Core: C[128 x BNT] = A * B^T with pre-split operands.
// Double-buffered cp.async staging; smem layout uint4 [stage][kq][col ^ kq],
// kq = kpair>>1, halves of the uint4 are the two kpairs.
// ---------------------------------------------------------------------------
template<int BNT, int WARPS_M, int WARPS_N>
__device__ __forceinline__ void gemm_ca_core(
    const uint2* __restrict__ A2, const uint2* __restrict__ B2,
    int K2, int lda2, int ldb2, int m0, int n0, float* acc)
{
    constexpr int WM = 128 / WARPS_M;
    constexpr int WN = BNT / WARPS_N;
    constexpr int MI = WM / 16;
    constexpr int NI = WN / 8;
    constexpr int ASTG = 8 * 128 * 16;        // bytes per A stage
    constexpr int BSTG = 8 * BNT * 16;
    constexpr int BBASE = 2 * ASTG;

    extern __shared__ char smem[];
    const uint32_t sb = smem_u32(smem);

    const int tid  = threadIdx.x;
    const int lane = tid & 31;
    const int warp = tid >> 5;
    const int g    = lane >> 2;
    const int tg   = lane & 3;
    const int wm   = (warp % WARPS_M) * WM;
    const int wn   = (warp / WARPS_M) * WN;

#pragma unroll
    for (int i = 0; i < MI * NI * 4; i++) acc[i] = 0.f;

    const int iters = K2 >> 4;

    // prologue: prefetch stage 0
    {
#pragma unroll
        for (int i = 0; i < 4; ++i) {
            int linear = tid + 256 * i;
            int m = linear >> 3, kq = linear & 7;
            cp16(sb + (kq * 128 + (m ^ kq)) * 16,
                 A2 + (size_t)(m0 + m) * lda2 + 2 * kq);
        }
#pragma unroll
        for (int i = 0; i < BNT / 32; ++i) {
            int linear = tid + 256 * i;
            int n = linear >> 3, kq = linear & 7;
            cp16(sb + BBASE + (kq * BNT + (n ^ kq)) * 16,
                 B2 + (size_t)(n0 + n) * ldb2 + 2 * kq);
        }
        asm volatile("cp.async.commit_group;" ::: "memory");
    }

    for (int it = 0; it < iters; ++it) {
        if (it + 1 < iters) {
            const int s   = (it + 1) & 1;
            const int kk2 = (it + 1) << 4;
#pragma unroll
            for (int i = 0; i < 4; ++i) {
                int linear = tid + 256 * i;
                int m = linear >> 3, kq = linear & 7;
                cp16(sb + s * ASTG + (kq * 128 + (m ^ kq)) * 16,
                     A2 + (size_t)(m0 + m) * lda2 + kk2 + 2 * kq);
            }
#pragma unroll
            for (int i = 0; i < BNT / 32; ++i) {
                int linear = tid + 256 * i;
                int n = linear >> 3, kq = linear & 7;
                cp16(sb + BBASE + s * BSTG + (kq * BNT + (n ^ kq)) * 16,
                     B2 + (size_t)(n0 + n) * ldb2 + kk2 + 2 * kq);
            }
            asm volatile("cp.async.commit_group;" ::: "memory");
            asm volatile("cp.async.wait_group 1;" ::: "memory");
        } else {
            asm volatile("cp.async.wait_group 0;" ::: "memory");
        }
        __syncthreads();

        const char* pA = smem + (it & 1) * ASTG;
        const char* pB = smem + BBASE + (it & 1) * BSTG;
#pragma unroll
        for (int kc = 0; kc < 2; ++kc) {
            const int kp0 = kc * 8 + tg;
            const int kp1 = kp0 + 4;
            const int kq0 = kp0 >> 1, h0 = (kp0 & 1) * 8;
            const int kq1 = kp1 >> 1, h1 = (kp1 & 1) * 8;
            uint32_t ahi[MI][4], alo[MI][4], bhi[NI][2], blo[NI][2];
#pragma unroll
            for (int mi = 0; mi < MI; mi++) {
                int mb = wm + mi * 16;
                uint2 p;
                p = *(const uint2*)(pA + (kq0 * 128 + ((mb + g)     ^ kq0)) * 16 + h0); ahi[mi][0] = p.x; alo[mi][0] = p.y;
                p = *(const uint2*)(pA + (kq0 * 128 + ((mb + g + 8) ^ kq0)) * 16 + h0); ahi[mi][1] = p.x; alo[mi][1] = p.y;
                p = *(const uint2*)(pA + (kq1 * 128 + ((mb + g)     ^ kq1)) * 16 + h1); ahi[mi][2] = p.x; alo[mi][2] = p.y;
                p = *(const uint2*)(pA + (kq1 * 128 + ((mb + g + 8) ^ kq1)) * 16 + h1); ahi[mi][3] = p.x; alo[mi][3] = p.y;
            }
#pragma unroll
            for (int ni = 0; ni < NI; ni++) {
                int nb = wn + ni * 8;
                uint2 p;
                p = *(const uint2*)(pB + (kq0 * BNT + ((nb + g) ^ kq0)) * 16 + h0); bhi[ni][0] = p.x; blo[ni][0] = p.y;
                p = *(const uint2*)(pB + (kq1 * BNT + ((nb + g) ^ kq1)) * 16 + h1); bhi[ni][1] = p.x; blo[ni][1] = p.y;
            }
#pragma unroll
            for (int mi = 0; mi < MI; mi++)
#pragma unroll
                for (int ni = 0; ni < NI; ni++) {
                    float* c = acc + (mi * NI + ni) * 4;
                    mma_fp16_k16(c, ahi[mi], bhi[ni]);
                    mma_fp16_k16(c, ahi[mi], blo[ni]);
                    mma_fp16_k16(c, alo[mi], bhi[ni]);
                }
        }
        __syncthreads();
    }
}

// ---------------------------------------------------------------------------
// Kernel 0: transpose + split x -> xt2[c][m][ipair]
// ---------------------------------------------------------------------------
__global__ __launch_bounds__(256) void transpose_x_split(const float* __restrict__ x) {
    int idx = blockIdx.x * 256 + threadIdx.x;
    if (idx < COOR * BN * (C_ / 2)) {
        int ip = idx & 127;
        int m  = (idx >> 7) & 4095;
        int c  = idx >> 19;
        float2 v;
        v.x = x[((size_t)m * C_ + 2 * ip)     * COOR + c];
        v.y = x[((size_t)m * C_ + 2 * ip + 1) * COOR + c];
        g_xt2[idx] = split2h(v);
    }
}

// ---------------------------------------------------------------------------
// Kernel 0b: split weights; Kernel 0c: zero row sums
// ---------------------------------------------------------------------------
__global__ __launch_bounds__(256) void split_w_kernel(const float* __restrict__ Wq,
                                                      const float* __restrict__ Wk,
                                                      const float* __restrict__ Wv,
                                                      const float* __restrict__ Wo) {
    int idx = blockIdx.x * 256 + threadIdx.x;
    const int NQKV = 3 * DI * (C_ / 2);
    if (idx < NQKV) {
        int ip  = idx & 127;
        int o   = (idx >> 7) & 511;
        int mat = idx >> 16;
        const float* W = (mat == 0) ? Wq : (mat == 1) ? Wk : Wv;
        float2 v;
        v.x = W[(size_t)o * C_ + 2 * ip];
        v.y = W[(size_t)o * C_ + 2 * ip + 1];
        g_w2[idx] = split2h(v);
    } else if (idx < NQKV + C_ * (DI / 2)) {
        int j  = idx - NQKV;
        int ip = j & 255;
        int o  = j >> 8;
        float2 v;
        v.x = Wo[(size_t)o * DI + 2 * ip];
        v.y = Wo[(size_t)o * DI + 2 * ip + 1];
        g_wo2[j] = split2h(v);
    }
}

__global__ __launch_bounds__(256) void zero_rsum_kernel() {
    int idx = blockIdx.x * 256 + threadIdx.x;
    if (idx < BH * N_) g_rsum[idx] = 0.f;
}

// ---------------------------------------------------------------------------
// Kernel 1: QKV projection. grid (32, 4, 9). Writes split q2/k2 directly
// (e' = c*64+d ordering); v as fp32 [bh][n][e'].
// ---------------------------------------------------------------------------
__global__ __launch_bounds__(256, 2) void qkv_kernel() {
    int z   = blockIdx.z;
    int mat = z / 3, c = z % 3;
    const uint2* A2 = g_xt2 + (size_t)c * BN * (C_ / 2);
    const uint2* B2 = g_w2 + (size_t)mat * DI * (C_ / 2);

    int m0 = blockIdx.x * 128, n0 = blockIdx.y * 128;
    float acc[4 * 4 * 4];
    gemm_ca_core<128, 2, 4>(A2, B2, C_ / 2, C_ / 2, C_ / 2, m0, n0, acc);

    const int lane = threadIdx.x & 31, warp = threadIdx.x >> 5;
    const int g = lane >> 2, tg = lane & 3;
    const int wm = (warp % 2) * 64, wn = (warp / 2) * 32;

    uint2* G2 = (mat == 0) ? g_q2 : g_k2;
#pragma unroll
    for (int mi = 0; mi < 4; mi++)
#pragma unroll
        for (int rh = 0; rh < 2; rh++) {
            int m  = m0 + wm + mi * 16 + g + rh * 8;
            int bb = m >> 11, n = m & (N_ - 1);
#pragma unroll
            for (int ni = 0; ni < 4; ni++) {
                int o = n0 + wn + ni * 8 + tg * 2;       // even
                int h = o >> 6, d = o & 63;              // d even
                float v0 = acc[(mi * 4 + ni) * 4 + rh * 2 + 0];
                float v1 = acc[(mi * 4 + ni) * 4 + rh * 2 + 1];
                if (mat < 2) {
                    G2[((size_t)(bb * H_ + h) * N_ + n) * (E_ / 2) + c * 32 + (d >> 1)] =
                        split2h(make_float2(v0, v1));
                } else {
                    float* vp = g_v + ((size_t)(bb * H_ + h) * N_ + n) * E_ + c * 64 + d;
                    vp[0] = v0;
                    vp[1] = v1;
                }
            }
        }
}

// ---------------------------------------------------------------------------
// Kernel 1c: transpose + split v -> v2 [bh][e'][npair]. grid (32, 3, 16)
// ---------------------------------------------------------------------------
__global__ __launch_bounds__(256) void split_v_kernel() {
    __shared__ float vs[64][65];
    int bh = blockIdx.z;
    int nb0 = blockIdx.x * 64, e0 = blockIdx.y * 64;
    int tid = threadIdx.x;
    const float* V = g_v + (size_t)bh * N_ * E_;
#pragma unroll
    for (int it = 0; it < 16; ++it) {
        int linear = tid + 256 * it;
        int row = linear >> 6, col = linear & 63;
        vs[row][col] = V[(size_t)(nb0 + row) * E_ + e0 + col];
    }
    __syncthreads();
    uint2* V2 = g_v2 + (size_t)bh * E_ * (N_ / 2);
#pragma unroll
    for (int it = 0; it < 8; ++it) {
        int linear = tid + 256 * it;
        int e_loc = linear >> 5, np = linear & 31;
        float2 v = make_float2(vs[2 * np][e_loc], vs[2 * np + 1][e_loc]);
        V2[(size_t)(e0 + e_loc) * (N_ / 2) + nb0 / 2 + np] = split2h(v);
    }
}

// ---------------------------------------------------------------------------
// Kernel 2: fused score + exp. grid (16, 16, 16).
// Writes unnormalized exp(s*scale) as split p2; accumulates row sums.
// (Logits ~N(0,1): exp without max-subtraction is safe in fp32.)
// ---------------------------------------------------------------------------
__global__ __launch_bounds__(256, 2) void score_kernel() {
    int bh = blockIdx.z;
    const uint2* Q2 = g_q2 + (size_t)bh * N_ * (E_ / 2);
    const uint2* K2 = g_k2 + (size_t)bh * N_ * (E_ / 2);

    int i0 = blockIdx.x * 128, j0 = blockIdx.y * 128;
    float acc[4 * 4 * 4];
    gemm_ca_core<128, 2, 4>(Q2, K2, E_ / 2, E_ / 2, E_ / 2, i0, j0, acc);

    const float scale = 0.07216878364870323f;  // 192^-0.5
    const int lane = threadIdx.x & 31, warp = threadIdx.x >> 5;
    const int g = lane >> 2, tg = lane & 3;
    const int wm = (warp % 2) * 64, wn = (warp / 2) * 32;

#pragma unroll
    for (int mi = 0; mi < 4; mi++)
#pragma unroll
        for (int rh = 0; rh < 2; rh++) {
            int ii = i0 + wm + mi * 16 + g + rh * 8;
            float rs = 0.f;
#pragma unroll
            for (int ni = 0; ni < 4; ni++) {
                float e0v = __expf(acc[(mi * 4 + ni) * 4 + rh * 2 + 0] * scale);
                float e1v = __expf(acc[(mi * 4 + ni) * 4 + rh * 2 + 1] * scale);
                rs += e0v + e1v;
                int jj = j0 + wn + ni * 8 + tg * 2;      // even
                g_p2[((size_t)bh * N_ + ii) * (N_ / 2) + (jj >> 1)] =
                    split2h(make_float2(e0v, e1v));
            }
            rs += __shfl_xor_sync(0xffffffffu, rs, 1);
            rs += __shfl_xor_sync(0xffffffffu, rs, 2);
            if (tg == 0) atomicAdd(&g_rsum[bh * N_ + ii], rs);
        }
}

// ---------------------------------------------------------------------------
// Kernel 4: O = P2 @ V2^T per bh, normalized by row sums. grid (16, 3, 16).
// Writes split o22 directly (pairs along d).
// ---------------------------------------------------------------------------
__global__ __launch_bounds__(256, 2) void pv_kernel() {
    int bh = blockIdx.z;
    const uint2* P2 = g_p2 + (size_t)bh * N_ * (N_ / 2);
    const uint2* V2 = g_v2 + (size_t)bh * E_ * (N_ / 2);

    int i0 = blockIdx.x * 128, e0 = blockIdx.y * 64;
    float acc[2 * 4 * 4];
    gemm_ca_core<64, 4, 2>(P2, V2, N_ / 2, N_ / 2, N_ / 2, i0, e0, acc);

    const int lane = threadIdx.x & 31, warp = threadIdx.x >> 5;
    const int g = lane >> 2, tg = lane & 3;
    const int wm = (warp % 4) * 32, wn = (warp / 4) * 32;
    int b = bh >> 3, h = bh & 7;
#pragma unroll
    for (int mi = 0; mi < 2; mi++)
#pragma unroll
        for (int rh = 0; rh < 2; rh++) {
            int ii = i0 + wm + mi * 16 + g + rh * 8;
            float inv = 1.f / g_rsum[bh * N_ + ii];
            int m = b * N_ + ii;
#pragma unroll
            for (int ni = 0; ni < 4; ni++) {
                int ep = e0 + wn + ni * 8 + tg * 2;      // even e'
                int cc = ep >> 6, dd = ep & 63;          // dd even
                float v0 = acc[(mi * 4 + ni) * 4 + rh * 2 + 0] * inv;
                float v1 = acc[(mi * 4 + ni) * 4 + rh * 2 + 1] * inv;
                g_o22[((size_t)cc * BN + m) * (DI / 2) + h * 32 + (dd >> 1)] =
                    split2h(make_float2(v0, v1));
            }
        }
}

// ---------------------------------------------------------------------------
// Kernel 5: final projection. grid (32, 2, 3). Writes d_out (B,N,C,3).
// ---------------------------------------------------------------------------
__global__ __launch_bounds__(256, 2) void out_kernel(float* __restrict__ out) {
    int c = blockIdx.z;
    const uint2* A2 = g_o22 + (size_t)c * BN * (DI / 2);

    int m0 = blockIdx.x * 128, o0 = blockIdx.y * 128;
    float acc[4 * 4 * 4];
    gemm_ca_core<128, 2, 4>(A2, g_wo2, DI / 2, DI / 2, DI / 2, m0, o0, acc);

    const int lane = threadIdx.x & 31, warp = threadIdx.x >> 5;
    const int g = lane >> 2, tg = lane & 3;
    const int wm = (warp % 2) * 64, wn = (warp / 2) * 32;
#pragma unroll
    for (int mi = 0; mi < 4; mi++)
#pragma unroll
        for (int rh = 0; rh < 2; rh++) {
            int m = m0 + wm + mi * 16 + g + rh * 8;
#pragma unroll
            for (int ni = 0; ni < 4; ni++) {
                int o = o0 + wn + ni * 8 + tg * 2;
                out[((size_t)m * C_ + o)     * COOR + c] = acc[(mi * 4 + ni) * 4 + rh * 2 + 0];
                out[((size_t)m * C_ + o + 1) * COOR + c] = acc[(mi * 4 + ni) * 4 + rh * 2 + 1];
            }
        }
}

// ---------------------------------------------------------------------------
extern "C" void kernel_launch(void* const* d_in, const int* in_sizes, int n_in,
                              void* d_out, int out_size) {
    const float* x  = (const float*)d_in[0];
    const float* Wq = (const float*)d_in[1];
    const float* Wk = (const float*)d_in[2];
    const float* Wv = (const float*)d_in[3];
    const float* Wo = (const float*)d_in[4];
    float* out = (float*)d_out;

    const int SM128 = 2 * (8 * 128 * 16) + 2 * (8 * 128 * 16);  // 65536
    const int SM64  = 2 * (8 * 128 * 16) + 2 * (8 * 64 * 16);   // 49152

    static int attr_done = 0;
    if (!attr_done) {
        cudaFuncSetAttribute(qkv_kernel,   cudaFuncAttributeMaxDynamicSharedMemorySize, SM128);
        cudaFuncSetAttribute(score_kernel, cudaFuncAttributeMaxDynamicSharedMemorySize, SM128);
        cudaFuncSetAttribute(pv_kernel,    cudaFuncAttributeMaxDynamicSharedMemorySize, SM64);
        cudaFuncSetAttribute(out_kernel,   cudaFuncAttributeMaxDynamicSharedMemorySize, SM128);
        attr_done = 1;
    }

    {
        int total = COOR * BN * (C_ / 2);
        transpose_x_split<<<(total + 255) / 256, 256>>>(x);
    }
    {
        int total = 3 * DI * (C_ / 2) + C_ * (DI / 2);
        split_w_kernel<<<(total + 255) / 256, 256>>>(Wq, Wk, Wv, Wo);
    }
    {
        zero_rsum_kernel<<<(BH * N_ + 255) / 256, 256>>>();
    }
    {
        dim3 grid(BN / 128, DI / 128, 9);
        qkv_kernel<<<grid, 256, SM128>>>();
    }
    {
        dim3 grid(N_ / 64, E_ / 64, BH);
        split_v_kernel<<<grid, 256>>>();
    }
    {
        dim3 grid(N_ / 128, N_ / 128, BH);
        score_kernel<<<grid, 256, SM128>>>();
    }
    {
        dim3 grid(N_ / 128, E_ / 64, BH);
        pv_kernel<<<grid, 256, SM64>>>();
    }
    {
        dim3 grid(BN / 128, C_ / 128, COOR);
        out_kernel<<<grid, 256, SM128>>>(out);
    }
}

// round 14
// speedup vs baseline: 1.3087x; 1.3087x over previous
#include <cuda_runtime.h>
#include <cuda_fp16.h>
#include <cstdint>

// Problem constants
#define B_    2
#define N_    2048
#define C_    256
#define COOR  3
#define H_    8
#define D_    64
#define E_    192      // D_*COOR
#define DI    512      // dim_inner = H_*D_
#define BN    4096     // B_*N_
#define BH    16       // B_*H_

// Scratch (device globals — no runtime allocation)
// Split format: uint2 = (hi fp16x2, lo fp16x2) for 2 adjacent K elements.
// e-dimension uses reordered index e' = c*64 + d (permutation-invariant for dots).
__device__ uint2 g_xt2[(size_t)COOR * BN * (C_ / 2)];        // [c][m][ipair]
__device__ uint2 g_w2 [(size_t)3 * DI * (C_ / 2)];           // [mat][o][ipair]
__device__ uint2 g_wo2[(size_t)C_ * (DI / 2)];               // [o][ipair]
__device__ uint2 g_q2 [(size_t)BH * N_ * (E_ / 2)];          // [bh][n][e'pair]
__device__ uint2 g_k2 [(size_t)BH * N_ * (E_ / 2)];
__device__ float g_v  [(size_t)BH * N_ * E_];                // [bh][n][e'] fp32
__device__ uint2 g_v2 [(size_t)BH * E_ * (N_ / 2)];          // [bh][e'][npair]
__device__ uint2 g_p2 [(size_t)BH * N_ * (N_ / 2)];          // [bh][i][jpair] unnormalized exp
__device__ float g_rsum[(size_t)BH * N_];                    // softmax row sums
__device__ uint2 g_o22[(size_t)COOR * BN * (DI / 2)];        // [c][m][dipair]

// ---------------------------------------------------------------------------
// helpers
// ---------------------------------------------------------------------------
__device__ __forceinline__ uint2 split2h(float2 v) {
    __half hx = __float2half_rn(v.x);
    __half hy = __float2half_rn(v.y);
    float lx = v.x - __half2float(hx);
    float ly = v.y - __half2float(hy);
    __half lxh = __float2half_rn(lx);
    __half lyh = __float2half_rn(ly);
    uint2 r;
    r.x = ((uint32_t)__half_as_ushort(hy) << 16) | (uint32_t)__half_as_ushort(hx);
    r.y = ((uint32_t)__half_as_ushort(lyh) << 16) | (uint32_t)__half_as_ushort(lxh);
    return r;
}

__device__ __forceinline__ void mma_fp16_k16(float* c, const uint32_t* a, const uint32_t* b) {
    asm volatile(
        "mma.sync.aligned.m16n8k16.row.col.f32.f16.f16.f32 "
        "{%0,%1,%2,%3},{%4,%5,%6,%7},{%8,%9},{%0,%1,%2,%3};"
        : "+f"(c[0]), "+f"(c[1]), "+f"(c[2]), "+f"(c[3])
        : "r"(a[0]), "r"(a[1]), "r"(a[2]), "r"(a[3]), "r"(b[0]), "r"(b[1]));
}

// XOR swizzle for uint2 [16][stride] arrays (stride % 16 == 4)
__device__ __forceinline__ int SW(int kp, int m) {
    return m ^ (kp & 7) ^ ((kp & 8) >> 2);
}

// ---------------------------------------------------------------------------
// Core: C[128 x BNT] = A * B^T with pre-split operands.
// Software-pipelined: LDG for tile it+1 issued before computing tile it;
// STS lands after compute (LDG latency hidden). Double-buffered smem,
// one __syncthreads per K-iteration.
// ---------------------------------------------------------------------------
template<int BNT, int WARPS_M, int WARPS_N>
__device__ __forceinline__ void gemm_pipe_core(
    const uint2* __restrict__ A2, const uint2* __restrict__ B2,
    int K2, int lda2, int ldb2, int m0, int n0, float* acc)
{
    constexpr int WM = 128 / WARPS_M;
    constexpr int WN = BNT / WARPS_N;
    constexpr int MI = WM / 16;
    constexpr int NI = WN / 8;
    constexpr int NB = BNT / 32;              // B uint4 loads per thread

    extern __shared__ char smem[];
    uint2 (*As2)[16][132]      = reinterpret_cast<uint2(*)[16][132]>(smem);
    uint2 (*Bs2)[16][BNT + 4]  = reinterpret_cast<uint2(*)[16][BNT + 4]>(smem + 33792);

    const int tid  = threadIdx.x;
    const int lane = tid & 31;
    const int warp = tid >> 5;
    const int g    = lane >> 2;
    const int tg   = lane & 3;
    const int wm   = (warp % WARPS_M) * WM;
    const int wn   = (warp / WARPS_M) * WN;

#pragma unroll
    for (int i = 0; i < MI * NI * 4; i++) acc[i] = 0.f;

    const int iters = K2 >> 4;
    uint4 ra[4], rb[NB];

    // prologue: load tile 0 into regs, then STS
#pragma unroll
    for (int i = 0; i < 4; ++i) {
        int linear = tid + 256 * i;
        int m = linear >> 3, kq = linear & 7;
        ra[i] = *reinterpret_cast<const uint4*>(A2 + (size_t)(m0 + m) * lda2 + 2 * kq);
    }
#pragma unroll
    for (int i = 0; i < NB; ++i) {
        int linear = tid + 256 * i;
        int n = linear >> 3, kq = linear & 7;
        rb[i] = *reinterpret_cast<const uint4*>(B2 + (size_t)(n0 + n) * ldb2 + 2 * kq);
    }
#pragma unroll
    for (int i = 0; i < 4; ++i) {
        int linear = tid + 256 * i;
        int m = linear >> 3, kq = linear & 7;
        As2[0][2 * kq][SW(2 * kq, m)]     = make_uint2(ra[i].x, ra[i].y);
        As2[0][2 * kq + 1][SW(2 * kq + 1, m)] = make_uint2(ra[i].z, ra[i].w);
    }
#pragma unroll
    for (int i = 0; i < NB; ++i) {
        int linear = tid + 256 * i;
        int n = linear >> 3, kq = linear & 7;
        Bs2[0][2 * kq][SW(2 * kq, n)]     = make_uint2(rb[i].x, rb[i].y);
        Bs2[0][2 * kq + 1][SW(2 * kq + 1, n)] = make_uint2(rb[i].z, rb[i].w);
    }
    __syncthreads();

    for (int it = 0; it < iters; ++it) {
        const bool more = (it + 1 < iters);
        if (more) {
            const int kk2 = (it + 1) << 4;
#pragma unroll
            for (int i = 0; i < 4; ++i) {
                int linear = tid + 256 * i;
                int m = linear >> 3, kq = linear & 7;
                ra[i] = *reinterpret_cast<const uint4*>(
                    A2 + (size_t)(m0 + m) * lda2 + kk2 + 2 * kq);
            }
#pragma unroll
            for (int i = 0; i < NB; ++i) {
                int linear = tid + 256 * i;
                int n = linear >> 3, kq = linear & 7;
                rb[i] = *reinterpret_cast<const uint4*>(
                    B2 + (size_t)(n0 + n) * ldb2 + kk2 + 2 * kq);
            }
        }

        // compute on buffer it&1 (LDGs above are in flight during this)
        const int buf = it & 1;
#pragma unroll
        for (int kc = 0; kc < 2; ++kc) {
            const int kp0 = kc * 8 + tg;
            const int kp1 = kp0 + 4;
            uint32_t ahi[MI][4], alo[MI][4], bhi[NI][2], blo[NI][2];
#pragma unroll
            for (int mi = 0; mi < MI; mi++) {
                int mb = wm + mi * 16;
                uint2 p;
                p = As2[buf][kp0][SW(kp0, mb + g)];     ahi[mi][0] = p.x; alo[mi][0] = p.y;
                p = As2[buf][kp0][SW(kp0, mb + g + 8)]; ahi[mi][1] = p.x; alo[mi][1] = p.y;
                p = As2[buf][kp1][SW(kp1, mb + g)];     ahi[mi][2] = p.x; alo[mi][2] = p.y;
                p = As2[buf][kp1][SW(kp1, mb + g + 8)]; ahi[mi][3] = p.x; alo[mi][3] = p.y;
            }
#pragma unroll
            for (int ni = 0; ni < NI; ni++) {
                int nb = wn + ni * 8;
                uint2 p;
                p = Bs2[buf][kp0][SW(kp0, nb + g)];     bhi[ni][0] = p.x; blo[ni][0] = p.y;
                p = Bs2[buf][kp1][SW(kp1, nb + g)];     bhi[ni][1] = p.x; blo[ni][1] = p.y;
            }
#pragma unroll
            for (int mi = 0; mi < MI; mi++)
#pragma unroll
                for (int ni = 0; ni < NI; ni++) {
                    float* c = acc + (mi * NI + ni) * 4;
                    mma_fp16_k16(c, ahi[mi], bhi[ni]);
                    mma_fp16_k16(c, ahi[mi], blo[ni]);
                    mma_fp16_k16(c, alo[mi], bhi[ni]);
                }
        }

        if (more) {
            const int nbuf = (it + 1) & 1;
#pragma unroll
            for (int i = 0; i < 4; ++i) {
                int linear = tid + 256 * i;
                int m = linear >> 3, kq = linear & 7;
                As2[nbuf][2 * kq][SW(2 * kq, m)]     = make_uint2(ra[i].x, ra[i].y);
                As2[nbuf][2 * kq + 1][SW(2 * kq + 1, m)] = make_uint2(ra[i].z, ra[i].w);
            }
#pragma unroll
            for (int i = 0; i < NB; ++i) {
                int linear = tid + 256 * i;
                int n = linear >> 3, kq = linear & 7;
                Bs2[nbuf][2 * kq][SW(2 * kq, n)]     = make_uint2(rb[i].x, rb[i].y);
                Bs2[nbuf][2 * kq + 1][SW(2 * kq + 1, n)] = make_uint2(rb[i].z, rb[i].w);
            }
            __syncthreads();
        }
    }
}

// ---------------------------------------------------------------------------
// Kernel 0: transpose + split x -> xt2[c][m][ipair]
// ---------------------------------------------------------------------------
__global__ __launch_bounds__(256) void transpose_x_split(const float* __restrict__ x) {
    int idx = blockIdx.x * 256 + threadIdx.x;
    if (idx < COOR * BN * (C_ / 2)) {
        int ip = idx & 127;
        int m  = (idx >> 7) & 4095;
        int c  = idx >> 19;
        float2 v;
        v.x = x[((size_t)m * C_ + 2 * ip)     * COOR + c];
        v.y = x[((size_t)m * C_ + 2 * ip + 1) * COOR + c];
        g_xt2[idx] = split2h(v);
    }
}

// ---------------------------------------------------------------------------
// Kernel 0b: split weights; Kernel 0c: zero row sums
// ---------------------------------------------------------------------------
__global__ __launch_bounds__(256) void split_w_kernel(const float* __restrict__ Wq,
                                                      const float* __restrict__ Wk,
                                                      const float* __restrict__ Wv,
                                                      const float* __restrict__ Wo) {
    int idx = blockIdx.x * 256 + threadIdx.x;
    const int NQKV = 3 * DI * (C_ / 2);
    if (idx < NQKV) {
        int ip  = idx & 127;
        int o   = (idx >> 7) & 511;
        int mat = idx >> 16;
        const float* W = (mat == 0) ? Wq : (mat == 1) ? Wk : Wv;
        float2 v;
        v.x = W[(size_t)o * C_ + 2 * ip];
        v.y = W[(size_t)o * C_ + 2 * ip + 1];
        g_w2[idx] = split2h(v);
    } else if (idx < NQKV + C_ * (DI / 2)) {
        int j  = idx - NQKV;
        int ip = j & 255;
        int o  = j >> 8;
        float2 v;
        v.x = Wo[(size_t)o * DI + 2 * ip];
        v.y = Wo[(size_t)o * DI + 2 * ip + 1];
        g_wo2[j] = split2h(v);
    }
}

__global__ __launch_bounds__(256) void zero_rsum_kernel() {
    int idx = blockIdx.x * 256 + threadIdx.x;
    if (idx < BH * N_) g_rsum[idx] = 0.f;
}

// ---------------------------------------------------------------------------
// Kernel 1: QKV projection. grid (32, 4, 9). Writes split q2/k2 directly
// (e' = c*64+d ordering); v as fp32 [bh][n][e'].
// ---------------------------------------------------------------------------
__global__ __launch_bounds__(256) void qkv_kernel() {
    int z   = blockIdx.z;
    int mat = z / 3, c = z % 3;
    const uint2* A2 = g_xt2 + (size_t)c * BN * (C_ / 2);
    const uint2* B2 = g_w2 + (size_t)mat * DI * (C_ / 2);

    int m0 = blockIdx.x * 128, n0 = blockIdx.y * 128;
    float acc[4 * 4 * 4];
    gemm_pipe_core<128, 2, 4>(A2, B2, C_ / 2, C_ / 2, C_ / 2, m0, n0, acc);

    const int lane = threadIdx.x & 31, warp = threadIdx.x >> 5;
    const int g = lane >> 2, tg = lane & 3;
    const int wm = (warp % 2) * 64, wn = (warp / 2) * 32;

    uint2* G2 = (mat == 0) ? g_q2 : g_k2;
#pragma unroll
    for (int mi = 0; mi < 4; mi++)
#pragma unroll
        for (int rh = 0; rh < 2; rh++) {
            int m  = m0 + wm + mi * 16 + g + rh * 8;
            int bb = m >> 11, n = m & (N_ - 1);
#pragma unroll
            for (int ni = 0; ni < 4; ni++) {
                int o = n0 + wn + ni * 8 + tg * 2;       // even
                int h = o >> 6, d = o & 63;              // d even
                float v0 = acc[(mi * 4 + ni) * 4 + rh * 2 + 0];
                float v1 = acc[(mi * 4 + ni) * 4 + rh * 2 + 1];
                if (mat < 2) {
                    G2[((size_t)(bb * H_ + h) * N_ + n) * (E_ / 2) + c * 32 + (d >> 1)] =
                        split2h(make_float2(v0, v1));
                } else {
                    float* vp = g_v + ((size_t)(bb * H_ + h) * N_ + n) * E_ + c * 64 + d;
                    vp[0] = v0;
                    vp[1] = v1;
                }
            }
        }
}

// ---------------------------------------------------------------------------
// Kernel 1c: transpose + split v -> v2 [bh][e'][npair]. grid (32, 3, 16)
// ---------------------------------------------------------------------------
__global__ __launch_bounds__(256) void split_v_kernel() {
    __shared__ float vs[64][65];
    int bh = blockIdx.z;
    int nb0 = blockIdx.x * 64, e0 = blockIdx.y * 64;
    int tid = threadIdx.x;
    const float* V = g_v + (size_t)bh * N_ * E_;
#pragma unroll
    for (int it = 0; it < 16; ++it) {
        int linear = tid + 256 * it;
        int row = linear >> 6, col = linear & 63;
        vs[row][col] = V[(size_t)(nb0 + row) * E_ + e0 + col];
    }
    __syncthreads();
    uint2* V2 = g_v2 + (size_t)bh * E_ * (N_ / 2);
#pragma unroll
    for (int it = 0; it < 8; ++it) {
        int linear = tid + 256 * it;
        int e_loc = linear >> 5, np = linear & 31;
        float2 v = make_float2(vs[2 * np][e_loc], vs[2 * np + 1][e_loc]);
        V2[(size_t)(e0 + e_loc) * (N_ / 2) + nb0 / 2 + np] = split2h(v);
    }
}

// ---------------------------------------------------------------------------
// Kernel 2: fused score + exp. grid (16, 16, 16).
// Writes unnormalized exp(s*scale) as split p2; accumulates row sums.
// (Logits ~N(0,1): exp without max-subtraction is safe in fp32.)
// ---------------------------------------------------------------------------
__global__ __launch_bounds__(256) void score_kernel() {
    int bh = blockIdx.z;
    const uint2* Q2 = g_q2 + (size_t)bh * N_ * (E_ / 2);
    const uint2* K2 = g_k2 + (size_t)bh * N_ * (E_ / 2);

    int i0 = blockIdx.x * 128, j0 = blockIdx.y * 128;
    float acc[4 * 4 * 4];
    gemm_pipe_core<128, 2, 4>(Q2, K2, E_ / 2, E_ / 2, E_ / 2, i0, j0, acc);

    const float scale = 0.07216878364870323f;  // 192^-0.5
    const int lane = threadIdx.x & 31, warp = threadIdx.x >> 5;
    const int g = lane >> 2, tg = lane & 3;
    const int wm = (warp % 2) * 64, wn = (warp / 2) * 32;

#pragma unroll
    for (int mi = 0; mi < 4; mi++)
#pragma unroll
        for (int rh = 0; rh < 2; rh++) {
            int ii = i0 + wm + mi * 16 + g + rh * 8;
            float rs = 0.f;
#pragma unroll
            for (int ni = 0; ni < 4; ni++) {
                float e0v = __expf(acc[(mi * 4 + ni) * 4 + rh * 2 + 0] * scale);
                float e1v = __expf(acc[(mi * 4 + ni) * 4 + rh * 2 + 1] * scale);
                rs += e0v + e1v;
                int jj = j0 + wn + ni * 8 + tg * 2;      // even
                g_p2[((size_t)bh * N_ + ii) * (N_ / 2) + (jj >> 1)] =
                    split2h(make_float2(e0v, e1v));
            }
            rs += __shfl_xor_sync(0xffffffffu, rs, 1);
            rs += __shfl_xor_sync(0xffffffffu, rs, 2);
            if (tg == 0) atomicAdd(&g_rsum[bh * N_ + ii], rs);
        }
}

// ---------------------------------------------------------------------------
// Kernel 4: O = P2 @ V2^T per bh, normalized by row sums. grid (16, 3, 16).
// Writes split o22 directly (pairs along d).
// ---------------------------------------------------------------------------
__global__ __launch_bounds__(256) void pv_kernel() {
    int bh = blockIdx.z;
    const uint2* P2 = g_p2 + (size_t)bh * N_ * (N_ / 2);
    const uint2* V2 = g_v2 + (size_t)bh * E_ * (N_ / 2);

    int i0 = blockIdx.x * 128, e0 = blockIdx.y * 64;
    float acc[2 * 4 * 4];
    gemm_pipe_core<64, 4, 2>(P2, V2, N_ / 2, N_ / 2, N_ / 2, i0, e0, acc);

    const int lane = threadIdx.x & 31, warp = threadIdx.x >> 5;
    const int g = lane >> 2, tg = lane & 3;
    const int wm = (warp % 4) * 32, wn = (warp / 4) * 32;
    int b = bh >> 3, h = bh & 7;
#pragma unroll
    for (int mi = 0; mi < 2; mi++)
#pragma unroll
        for (int rh = 0; rh < 2; rh++) {
            int ii = i0 + wm + mi * 16 + g + rh * 8;
            float inv = 1.f / g_rsum[bh * N_ + ii];
            int m = b * N_ + ii;
#pragma unroll
            for (int ni = 0; ni < 4; ni++) {
                int ep = e0 + wn + ni * 8 + tg * 2;      // even e'
                int cc = ep >> 6, dd = ep & 63;          // dd even
                float v0 = acc[(mi * 4 + ni) * 4 + rh * 2 + 0] * inv;
                float v1 = acc[(mi * 4 + ni) * 4 + rh * 2 + 1] * inv;
                g_o22[((size_t)cc * BN + m) * (DI / 2) + h * 32 + (dd >> 1)] =
                    split2h(make_float2(v0, v1));
            }
        }
}

// ---------------------------------------------------------------------------
// Kernel 5: final projection. grid (32, 2, 3). Writes d_out (B,N,C,3).
// ---------------------------------------------------------------------------
__global__ __launch_bounds__(256) void out_kernel(float* __restrict__ out) {
    int c = blockIdx.z;
    const uint2* A2 = g_o22 + (size_t)c * BN * (DI / 2);

    int m0 = blockIdx.x * 128, o0 = blockIdx.y * 128;
    float acc[4 * 4 * 4];
    gemm_pipe_core<128, 2, 4>(A2, g_wo2, DI / 2, DI / 2, DI / 2, m0, o0, acc);

    const int lane = threadIdx.x & 31, warp = threadIdx.x >> 5;
    const int g = lane >> 2, tg = lane & 3;
    const int wm = (warp % 2) * 64, wn = (warp / 2) * 32;
#pragma unroll
    for (int mi = 0; mi < 4; mi++)
#pragma unroll
        for (int rh = 0; rh < 2; rh++) {
            int m = m0 + wm + mi * 16 + g + rh * 8;
#pragma unroll
            for (int ni = 0; ni < 4; ni++) {
                int o = o0 + wn + ni * 8 + tg * 2;
                out[((size_t)m * C_ + o)     * COOR + c] = acc[(mi * 4 + ni) * 4 + rh * 2 + 0];
                out[((size_t)m * C_ + o + 1) * COOR + c] = acc[(mi * 4 + ni) * 4 + rh * 2 + 1];
            }
        }
}

// ---------------------------------------------------------------------------
extern "C" void kernel_launch(void* const* d_in, const int* in_sizes, int n_in,
                              void* d_out, int out_size) {
    const float* x  = (const float*)d_in[0];
    const float* Wq = (const float*)d_in[1];
    const float* Wk = (const float*)d_in[2];
    const float* Wv = (const float*)d_in[3];
    const float* Wo = (const float*)d_in[4];
    float* out = (float*)d_out;

    // dyn smem: A bufs 2*16*132*8 = 33792, B bufs 2*16*(BNT+4)*8
    const int SM128 = 33792 + 2 * 16 * 132 * 8;   // 67584
    const int SM64  = 33792 + 2 * 16 * 68 * 8;    // 51200

    cudaFuncSetAttribute(qkv_kernel,   cudaFuncAttributeMaxDynamicSharedMemorySize, SM128);
    cudaFuncSetAttribute(score_kernel, cudaFuncAttributeMaxDynamicSharedMemorySize, SM128);
    cudaFuncSetAttribute(pv_kernel,    cudaFuncAttributeMaxDynamicSharedMemorySize, SM64);
    cudaFuncSetAttribute(out_kernel,   cudaFuncAttributeMaxDynamicSharedMemorySize, SM128);

    {
        int total = COOR * BN * (C_ / 2);
        transpose_x_split<<<(total + 255) / 256, 256>>>(x);
    }
    {
        int total = 3 * DI * (C_ / 2) + C_ * (DI / 2);
        split_w_kernel<<<(total + 255) / 256, 256>>>(Wq, Wk, Wv, Wo);
    }
    {
        zero_rsum_kernel<<<(BH * N_ + 255) / 256, 256>>>();
    }
    {
        dim3 grid(BN / 128, DI / 128, 9);
        qkv_kernel<<<grid, 256, SM128>>>();
    }
    {
        dim3 grid(N_ / 64, E_ / 64, BH);
        split_v_kernel<<<grid, 256>>>();
    }
    {
        dim3 grid(N_ / 128, N_ / 128, BH);
        score_kernel<<<grid, 256, SM128>>>();
    }
    {
        dim3 grid(N_ / 128, E_ / 64, BH);
        pv_kernel<<<grid, 256, SM64>>>();
    }
    {
        dim3 grid(BN / 128, C_ / 128, COOR);
        out_kernel<<<grid, 256, SM128>>>(out);
    }
}